// round 2
// baseline (speedup 1.0000x reference)
#include <cuda_runtime.h>
#include <cuda_bf16.h>
#include <cstdint>

// ============================================================================
// ContrastiveLoss (N=4096, D=256, tau=0.1)
//   z = normalize(concat(x1,x2)) -> bf16
//   denom[r] = sum_j exp(mask * (z_r . z_j) / tau)   (diag -> exp(0)=1)
//   loss = mean_r( log(denom[r]) - pos[r]/tau )
// Fused mma.sync bf16 GEMM + exp + row-sum (no sim materialization).
// Target is compute_100 baseline PTX (no tcgen05 available at this vtarget).
// ============================================================================

#define TAU_INV 10.0f
static constexpr int NROWS = 4096;
static constexpr int TWO_N = 8192;
static constexpr int D     = 256;          // K
static constexpr int BM    = 128;          // rows per CTA strip
static constexpr int BN    = 128;          // cols per tile
static constexpr int NSPLIT = 2;           // column splits -> 128 CTAs
static constexpr int JT_PER_SPLIT = (TWO_N / BN) / NSPLIT;   // 32

// SMEM tiles: [128 rows][256 k] bf16, padded row stride 264 elems = 528 B
static constexpr int TSTRIDE_B = 528;                 // bytes per padded row
static constexpr int TILE_BYTES = BM * TSTRIDE_B;     // 67584
static constexpr int SMEM_TOTAL = 3 * TILE_BYTES;     // A + B0 + B1 = 202752

// ---------------- device scratch (allocation-free) --------------------------
__device__ uint32_t g_z[TWO_N * (D / 2)];   // bf16x2 words, [8192][128]
__device__ float    g_inv[TWO_N];
__device__ float    g_pos[NROWS];
__device__ float    g_denom[TWO_N];

// ---------------- PTX helpers ----------------------------------------------
__device__ __forceinline__ uint32_t smem_to_u32(const void* p) {
    uint32_t a;
    asm("{ .reg .u64 t; cvta.to.shared.u64 t, %1; cvt.u32.u64 %0, t; }"
        : "=r"(a) : "l"(p));
    return a;
}

__device__ __forceinline__ void cp_async16(uint32_t dst, const void* src) {
    asm volatile("cp.async.cg.shared.global [%0], [%1], 16;"
                 :: "r"(dst), "l"(src) : "memory");
}
#define CP_COMMIT() asm volatile("cp.async.commit_group;" ::: "memory")
#define CP_WAIT0()  asm volatile("cp.async.wait_group 0;" ::: "memory")

__device__ __forceinline__ void ldsm_x4(uint32_t* r, uint32_t addr) {
    asm volatile("ldmatrix.sync.aligned.m8n8.x4.shared.b16 {%0,%1,%2,%3}, [%4];"
                 : "=r"(r[0]), "=r"(r[1]), "=r"(r[2]), "=r"(r[3]) : "r"(addr));
}
__device__ __forceinline__ void ldsm_x2(uint32_t* r, uint32_t addr) {
    asm volatile("ldmatrix.sync.aligned.m8n8.x2.shared.b16 {%0,%1}, [%2];"
                 : "=r"(r[0]), "=r"(r[1]) : "r"(addr));
}

#define MMA16816(d, a, b) \
    asm volatile( \
        "mma.sync.aligned.m16n8k16.row.col.f32.bf16.bf16.f32 " \
        "{%0,%1,%2,%3}, {%4,%5,%6,%7}, {%8,%9}, {%0,%1,%2,%3};" \
        : "+f"((d)[0]), "+f"((d)[1]), "+f"((d)[2]), "+f"((d)[3]) \
        : "r"((a)[0]), "r"((a)[1]), "r"((a)[2]), "r"((a)[3]), \
          "r"((b)[0]), "r"((b)[1]))

__device__ __forceinline__ uint32_t pack_bf16x2(float lo, float hi) {
    uint32_t l = (uint32_t)__bfloat16_as_ushort(__float2bfloat16_rn(lo));
    uint32_t h = (uint32_t)__bfloat16_as_ushort(__float2bfloat16_rn(hi));
    return l | (h << 16);
}

// ---------------- Stage 1: row-normalize -> bf16 z, inv norms, zero denom ---
__global__ void norm_kernel(const float* __restrict__ x1, const float* __restrict__ x2) {
    int row  = blockIdx.x * 8 + threadIdx.y;          // 0..8191
    int lane = threadIdx.x;
    const float* src = (row < NROWS) ? (x1 + (size_t)row * D)
                                     : (x2 + (size_t)(row - NROWS) * D);
    const float4* s4 = reinterpret_cast<const float4*>(src);
    float4 a = s4[lane * 2];
    float4 b = s4[lane * 2 + 1];
    float ss = a.x * a.x + a.y * a.y + a.z * a.z + a.w * a.w
             + b.x * b.x + b.y * b.y + b.z * b.z + b.w * b.w;
    #pragma unroll
    for (int o = 16; o; o >>= 1) ss += __shfl_xor_sync(0xffffffffu, ss, o);
    float inv = 1.0f / fmaxf(sqrtf(ss), 1e-12f);
    if (lane == 0) { g_inv[row] = inv; g_denom[row] = 0.0f; }
    uint32_t* dst = g_z + (size_t)row * (D / 2) + lane * 4;
    dst[0] = pack_bf16x2(a.x * inv, a.y * inv);
    dst[1] = pack_bf16x2(a.z * inv, a.w * inv);
    dst[2] = pack_bf16x2(b.x * inv, b.y * inv);
    dst[3] = pack_bf16x2(b.z * inv, b.w * inv);
}

// ---------------- Stage 2: positive-pair dot in fp32 ------------------------
__global__ void pos_kernel(const float* __restrict__ x1, const float* __restrict__ x2) {
    int row  = blockIdx.x * 8 + threadIdx.y;          // 0..4095
    int lane = threadIdx.x;
    const float4* s1 = reinterpret_cast<const float4*>(x1 + (size_t)row * D);
    const float4* s2 = reinterpret_cast<const float4*>(x2 + (size_t)row * D);
    float4 a1 = s1[lane * 2], b1 = s1[lane * 2 + 1];
    float4 a2 = s2[lane * 2], b2 = s2[lane * 2 + 1];
    float d = a1.x * a2.x + a1.y * a2.y + a1.z * a2.z + a1.w * a2.w
            + b1.x * b2.x + b1.y * b2.y + b1.z * b2.z + b1.w * b2.w;
    #pragma unroll
    for (int o = 16; o; o >>= 1) d += __shfl_xor_sync(0xffffffffu, d, o);
    if (lane == 0) g_pos[row] = d * g_inv[row] * g_inv[row + NROWS];
}

// ---------------- tile loader: 128 rows x 256 bf16 (512B/row) ---------------
__device__ __forceinline__ void load_tile(uint32_t dst, int row0, int tid) {
    const char* src = reinterpret_cast<const char*>(g_z) + (size_t)row0 * 512;
    #pragma unroll
    for (int i = 0; i < 16; i++) {
        int idx = tid + i * 256;
        int r = idx >> 5, s = idx & 31;
        cp_async16(dst + r * TSTRIDE_B + s * 16, src + r * 512 + s * 16);
    }
}

// ---------------- Stage 3: fused GEMM + exp + row-sum ----------------------
__global__ __launch_bounds__(256, 1)
void gemm_kernel() {
    extern __shared__ char smem[];
    const int tid  = threadIdx.x;
    const int lane = tid & 31;
    const int warp = tid >> 5;
    const int wm   = warp >> 2;             // 0..1  (64-row half)
    const int wn   = warp & 3;              // 0..3  (32-col slice)
    const int cta_m = blockIdx.x;           // 0..63
    const int split = blockIdx.y;           // 0..1

    const uint32_t smem_u = smem_to_u32(smem);
    const uint32_t A_base = smem_u;
    const uint32_t B0 = smem_u + TILE_BYTES;
    const uint32_t B1 = smem_u + 2 * TILE_BYTES;

    // Prologue: A strip + first B tile
    load_tile(A_base, cta_m * BM, tid);
    CP_COMMIT();
    load_tile(B0, (split * JT_PER_SPLIT) * BN, tid);
    CP_COMMIT();

    // ldmatrix per-thread base offsets
    const uint32_t a_off = (uint32_t)((wm * 64 + (lane & 15)) * TSTRIDE_B + (lane >> 4) * 16);
    const uint32_t b_off = (uint32_t)((wn * 32 + (lane & 7)) * TSTRIDE_B + ((lane >> 3) & 1) * 16);

    float denom[8] = {0, 0, 0, 0, 0, 0, 0, 0};
    const int row0 = cta_m * BM + wm * 64;

    for (int j = 0; j < JT_PER_SPLIT; j++) {
        CP_WAIT0();
        __syncthreads();
        if (j + 1 < JT_PER_SPLIT) {
            uint32_t dstb = ((j + 1) & 1) ? B1 : B0;
            load_tile(dstb, (split * JT_PER_SPLIT + j + 1) * BN, tid);
            CP_COMMIT();
        }
        const uint32_t Ab = A_base + a_off;
        const uint32_t Bb = ((j & 1) ? B1 : B0) + b_off;

        float acc[4][4][4];
        #pragma unroll
        for (int mi = 0; mi < 4; mi++)
            #pragma unroll
            for (int ni = 0; ni < 4; ni++)
                #pragma unroll
                for (int e = 0; e < 4; e++) acc[mi][ni][e] = 0.0f;

        #pragma unroll
        for (int ks = 0; ks < 16; ks++) {
            uint32_t a[4][4], b[4][2];
            #pragma unroll
            for (int mi = 0; mi < 4; mi++)
                ldsm_x4(a[mi], Ab + mi * (16 * TSTRIDE_B) + ks * 32);
            #pragma unroll
            for (int ni = 0; ni < 4; ni++)
                ldsm_x2(b[ni], Bb + ni * (8 * TSTRIDE_B) + ks * 32);
            #pragma unroll
            for (int mi = 0; mi < 4; mi++)
                #pragma unroll
                for (int ni = 0; ni < 4; ni++)
                    MMA16816(acc[mi][ni], a[mi], b[ni]);
        }

        // Fused epilogue: exp and accumulate per-row denominators
        const int jg = split * JT_PER_SPLIT + j;
        const bool diag_tile = (jg == cta_m);
        const int col0 = jg * BN + wn * 32;
        #pragma unroll
        for (int mi = 0; mi < 4; mi++)
            #pragma unroll
            for (int ni = 0; ni < 4; ni++)
                #pragma unroll
                for (int e = 0; e < 4; e++) {
                    float v = __expf(acc[mi][ni][e] * TAU_INV);
                    if (diag_tile) {
                        int rloc = mi * 16 + (lane >> 2) + (e >> 1) * 8;
                        int c = col0 + ni * 8 + (lane & 3) * 2 + (e & 1);
                        if (c == row0 + rloc) v = 1.0f;   // diag -> exp(0)
                    }
                    denom[mi * 2 + (e >> 1)] += v;
                }
    }

    // Reduce across the 4 lanes of each quad (same rows, different cols)
    #pragma unroll
    for (int d = 0; d < 8; d++) {
        denom[d] += __shfl_xor_sync(0xffffffffu, denom[d], 1);
        denom[d] += __shfl_xor_sync(0xffffffffu, denom[d], 2);
    }
    if ((lane & 3) == 0) {
        #pragma unroll
        for (int d = 0; d < 8; d++) {
            int row = row0 + (d >> 1) * 16 + (d & 1) * 8 + (lane >> 2);
            atomicAdd(&g_denom[row], denom[d]);
        }
    }
}

// ---------------- Stage 4: loss = mean(log(denom) - pos/tau) ----------------
__global__ void finish_kernel(float* __restrict__ out) {
    __shared__ float red[32];
    int t = threadIdx.x;                    // 1024 threads
    float s = 0.0f;
    #pragma unroll
    for (int i = 0; i < 8; i++) {
        int r = t + i * 1024;
        s += logf(g_denom[r]) - g_pos[r & (NROWS - 1)] * TAU_INV;
    }
    #pragma unroll
    for (int o = 16; o; o >>= 1) s += __shfl_xor_sync(0xffffffffu, s, o);
    if ((t & 31) == 0) red[t >> 5] = s;
    __syncthreads();
    if (t < 32) {
        float v = red[t];
        #pragma unroll
        for (int o = 16; o; o >>= 1) v += __shfl_xor_sync(0xffffffffu, v, o);
        if (t == 0) out[0] = v * (1.0f / (float)TWO_N);
    }
}

// ---------------- launch ----------------------------------------------------
extern "C" void kernel_launch(void* const* d_in, const int* in_sizes, int n_in,
                              void* d_out, int out_size) {
    (void)in_sizes; (void)n_in; (void)out_size;
    const float* x1 = (const float*)d_in[0];
    const float* x2 = (const float*)d_in[1];
    float* out = (float*)d_out;

    cudaFuncSetAttribute(gemm_kernel,
                         cudaFuncAttributeMaxDynamicSharedMemorySize, SMEM_TOTAL);

    dim3 wb(32, 8);
    norm_kernel<<<TWO_N / 8, wb>>>(x1, x2);
    pos_kernel<<<NROWS / 8, wb>>>(x1, x2);
    dim3 grid(TWO_N / BM, NSPLIT);
    gemm_kernel<<<grid, 256, SMEM_TOTAL>>>();
    finish_kernel<<<1, 1024>>>(out);
}

// round 3
// speedup vs baseline: 1.6067x; 1.6067x over previous
#include <cuda_runtime.h>
#include <cuda_bf16.h>
#include <cstdint>

// ============================================================================
// ContrastiveLoss (N=4096, D=256, tau=0.1)
//   z = normalize(concat(x1,x2)) -> bf16
//   denom[r] = sum_j exp(mask * (z_r . z_j) / tau)   (diag -> exp(0)=1)
//   loss = mean_r( log(denom[r]) - pos[r]/tau )
// Symmetric-triangle fused mma.sync bf16 GEMM: only tiles J>=I computed;
// off-diagonal tiles feed row sums (strip I) AND column sums (strip J).
// ============================================================================

#define TAU_INV 10.0f
static constexpr int NROWS = 4096;
static constexpr int TWO_N = 8192;
static constexpr int D     = 256;          // K
static constexpr int BM    = 128;
static constexpr int BN    = 128;
static constexpr int NSTRIP = TWO_N / BM;            // 64
static constexpr int NUM_TILES = NSTRIP * (NSTRIP + 1) / 2;   // 2080
static constexpr int NUM_CTAS  = 148;

// SMEM tiles: [128 rows][256 k] bf16, padded row stride 264 elems = 528 B
static constexpr int TSTRIDE_B = 528;
static constexpr int TILE_BYTES = BM * TSTRIDE_B;     // 67584
static constexpr int SMEM_TOTAL = 3 * TILE_BYTES;     // A + B0 + B1 = 202752

// ---------------- device scratch (allocation-free) --------------------------
__device__ uint32_t g_z[TWO_N * (D / 2)];   // bf16x2 words, [8192][128]
__device__ float    g_inv[TWO_N];
__device__ float    g_pos[NROWS];
__device__ float    g_denom[TWO_N];
__device__ unsigned g_done;

// ---------------- PTX helpers ----------------------------------------------
__device__ __forceinline__ uint32_t smem_to_u32(const void* p) {
    uint32_t a;
    asm("{ .reg .u64 t; cvta.to.shared.u64 t, %1; cvt.u32.u64 %0, t; }"
        : "=r"(a) : "l"(p));
    return a;
}

__device__ __forceinline__ void cp_async16(uint32_t dst, const void* src) {
    asm volatile("cp.async.cg.shared.global [%0], [%1], 16;"
                 :: "r"(dst), "l"(src) : "memory");
}
#define CP_COMMIT() asm volatile("cp.async.commit_group;" ::: "memory")
#define CP_WAIT0()  asm volatile("cp.async.wait_group 0;" ::: "memory")
#define CP_WAIT1()  asm volatile("cp.async.wait_group 1;" ::: "memory")

__device__ __forceinline__ void ldsm_x4(uint32_t* r, uint32_t addr) {
    asm volatile("ldmatrix.sync.aligned.m8n8.x4.shared.b16 {%0,%1,%2,%3}, [%4];"
                 : "=r"(r[0]), "=r"(r[1]), "=r"(r[2]), "=r"(r[3]) : "r"(addr));
}
__device__ __forceinline__ void ldsm_x2(uint32_t* r, uint32_t addr) {
    asm volatile("ldmatrix.sync.aligned.m8n8.x2.shared.b16 {%0,%1}, [%2];"
                 : "=r"(r[0]), "=r"(r[1]) : "r"(addr));
}

#define MMA16816(d, a, b) \
    asm volatile( \
        "mma.sync.aligned.m16n8k16.row.col.f32.bf16.bf16.f32 " \
        "{%0,%1,%2,%3}, {%4,%5,%6,%7}, {%8,%9}, {%0,%1,%2,%3};" \
        : "+f"((d)[0]), "+f"((d)[1]), "+f"((d)[2]), "+f"((d)[3]) \
        : "r"((a)[0]), "r"((a)[1]), "r"((a)[2]), "r"((a)[3]), \
          "r"((b)[0]), "r"((b)[1]))

__device__ __forceinline__ uint32_t pack_bf16x2(float lo, float hi) {
    uint32_t l = (uint32_t)__bfloat16_as_ushort(__float2bfloat16_rn(lo));
    uint32_t h = (uint32_t)__bfloat16_as_ushort(__float2bfloat16_rn(hi));
    return l | (h << 16);
}

// Balanced triangle enumeration: pair p in [0,32) = strip p (64-p tiles,
// J=p..63) followed by strip 63-p (p+1 tiles, J=63-p..63). 65 tiles per pair.
__device__ __forceinline__ void decode_tile(int t, int& I, int& J) {
    int p   = t / 65;
    int idx = t - p * 65;
    int na  = 64 - p;
    if (idx < na) { I = p;      J = p + idx; }
    else          { I = 63 - p; J = 63 - p + (idx - na); }
}

// ---------------- Stage 1: row-normalize -> bf16 z, inv norms, zero denom ---
__global__ void norm_kernel(const float* __restrict__ x1, const float* __restrict__ x2) {
    int row  = blockIdx.x * 8 + threadIdx.y;          // 0..8191
    int lane = threadIdx.x;
    if (row == 0 && lane == 0) g_done = 0;
    const float* src = (row < NROWS) ? (x1 + (size_t)row * D)
                                     : (x2 + (size_t)(row - NROWS) * D);
    const float4* s4 = reinterpret_cast<const float4*>(src);
    float4 a = s4[lane * 2];
    float4 b = s4[lane * 2 + 1];
    float ss = a.x * a.x + a.y * a.y + a.z * a.z + a.w * a.w
             + b.x * b.x + b.y * b.y + b.z * b.z + b.w * b.w;
    #pragma unroll
    for (int o = 16; o; o >>= 1) ss += __shfl_xor_sync(0xffffffffu, ss, o);
    float inv = 1.0f / fmaxf(sqrtf(ss), 1e-12f);
    if (lane == 0) { g_inv[row] = inv; g_denom[row] = 0.0f; }
    uint32_t* dst = g_z + (size_t)row * (D / 2) + lane * 4;
    dst[0] = pack_bf16x2(a.x * inv, a.y * inv);
    dst[1] = pack_bf16x2(a.z * inv, a.w * inv);
    dst[2] = pack_bf16x2(b.x * inv, b.y * inv);
    dst[3] = pack_bf16x2(b.z * inv, b.w * inv);
}

// ---------------- Stage 2: positive-pair dot in fp32 ------------------------
__global__ void pos_kernel(const float* __restrict__ x1, const float* __restrict__ x2) {
    int row  = blockIdx.x * 8 + threadIdx.y;          // 0..4095
    int lane = threadIdx.x;
    const float4* s1 = reinterpret_cast<const float4*>(x1 + (size_t)row * D);
    const float4* s2 = reinterpret_cast<const float4*>(x2 + (size_t)row * D);
    float4 a1 = s1[lane * 2], b1 = s1[lane * 2 + 1];
    float4 a2 = s2[lane * 2], b2 = s2[lane * 2 + 1];
    float d = a1.x * a2.x + a1.y * a2.y + a1.z * a2.z + a1.w * a2.w
            + b1.x * b2.x + b1.y * b2.y + b1.z * b2.z + b1.w * b2.w;
    #pragma unroll
    for (int o = 16; o; o >>= 1) d += __shfl_xor_sync(0xffffffffu, d, o);
    if (lane == 0) g_pos[row] = d * g_inv[row] * g_inv[row + NROWS];
}

// ---------------- tile loader: 128 rows x 256 bf16 (512B/row) ---------------
__device__ __forceinline__ void load_tile(uint32_t dst, int row0, int tid) {
    const char* src = reinterpret_cast<const char*>(g_z) + (size_t)row0 * 512;
    #pragma unroll
    for (int i = 0; i < 16; i++) {
        int idx = tid + i * 256;
        int r = idx >> 5, s = idx & 31;
        cp_async16(dst + r * TSTRIDE_B + s * 16, src + r * 512 + s * 16);
    }
}

// ---------------- Stage 3: triangular fused GEMM + exp + sums ---------------
__global__ __launch_bounds__(256, 1)
void gemm_kernel(float* __restrict__ out) {
    extern __shared__ char smem[];
    const int tid  = threadIdx.x;
    const int lane = tid & 31;
    const int warp = tid >> 5;
    const int wm   = warp >> 2;             // 0..1  (64-row half)
    const int wn   = warp & 3;              // 0..3  (32-col slice)
    const int cta  = blockIdx.x;

    const uint32_t smem_u = smem_to_u32(smem);
    const uint32_t A_base = smem_u;
    const uint32_t Bbuf[2] = { smem_u + TILE_BYTES, smem_u + 2 * TILE_BYTES };

    const int t0 = (cta * NUM_TILES) / NUM_CTAS;
    const int t1 = ((cta + 1) * NUM_TILES) / NUM_CTAS;

    int I, J;
    decode_tile(t0, I, J);
    load_tile(A_base, I * BM, tid);
    load_tile(Bbuf[0], J * BN, tid);
    CP_COMMIT();
    int cur = 0;

    const uint32_t a_off = (uint32_t)((wm * 64 + (lane & 15)) * TSTRIDE_B + (lane >> 4) * 16);
    const uint32_t b_off = (uint32_t)((wn * 32 + (lane & 7)) * TSTRIDE_B + ((lane >> 3) & 1) * 16);

    float denom[8] = {0, 0, 0, 0, 0, 0, 0, 0};

    for (int t = t0; t < t1; t++) {
        int nI = I, nJ = J;
        const bool have = (t + 1 < t1);
        if (have) decode_tile(t + 1, nI, nJ);

        if (have && nI == I) {
            load_tile(Bbuf[cur ^ 1], nJ * BN, tid);
            CP_COMMIT();
            CP_WAIT1();
        } else {
            CP_WAIT0();
        }
        __syncthreads();

        // ---- GEMM: 16 K-steps ----
        const uint32_t Ab = A_base + a_off;
        const uint32_t Bb = Bbuf[cur] + b_off;
        float acc[4][4][4];
        #pragma unroll
        for (int mi = 0; mi < 4; mi++)
            #pragma unroll
            for (int ni = 0; ni < 4; ni++)
                #pragma unroll
                for (int e = 0; e < 4; e++) acc[mi][ni][e] = 0.0f;

        #pragma unroll
        for (int ks = 0; ks < 16; ks++) {
            uint32_t a[4][4], b[4][2];
            #pragma unroll
            for (int mi = 0; mi < 4; mi++)
                ldsm_x4(a[mi], Ab + mi * (16 * TSTRIDE_B) + ks * 32);
            #pragma unroll
            for (int ni = 0; ni < 4; ni++)
                ldsm_x2(b[ni], Bb + ni * (8 * TSTRIDE_B) + ks * 32);
            #pragma unroll
            for (int mi = 0; mi < 4; mi++)
                #pragma unroll
                for (int ni = 0; ni < 4; ni++)
                    MMA16816(acc[mi][ni], a[mi], b[ni]);
        }

        // ---- epilogue: exp; row sums always, col sums when I < J ----
        const bool diag = (I == J);
        const int row0 = I * BM + wm * 64;
        const int col0 = J * BN + wn * 32;
        float cs[8] = {0, 0, 0, 0, 0, 0, 0, 0};
        #pragma unroll
        for (int mi = 0; mi < 4; mi++)
            #pragma unroll
            for (int ni = 0; ni < 4; ni++)
                #pragma unroll
                for (int e = 0; e < 4; e++) {
                    float v = __expf(acc[mi][ni][e] * TAU_INV);
                    if (diag) {
                        int r = row0 + mi * 16 + (e >> 1) * 8 + (lane >> 2);
                        int c = col0 + ni * 8 + (lane & 3) * 2 + (e & 1);
                        if (c == r) v = 1.0f;            // diag -> exp(0)
                    }
                    denom[mi * 2 + (e >> 1)] += v;
                    cs[ni * 2 + (e & 1)] += v;
                }
        if (!diag) {
            // reduce col partials over row-carrying lane bits (2,3,4)
            #pragma unroll
            for (int k = 0; k < 8; k++) {
                cs[k] += __shfl_xor_sync(0xffffffffu, cs[k], 4);
                cs[k] += __shfl_xor_sync(0xffffffffu, cs[k], 8);
                cs[k] += __shfl_xor_sync(0xffffffffu, cs[k], 16);
            }
            if (lane < 4) {
                #pragma unroll
                for (int k = 0; k < 8; k++)
                    atomicAdd(&g_denom[col0 + (k >> 1) * 8 + lane * 2 + (k & 1)], cs[k]);
            }
        }

        // ---- flush row denominators when strip changes (or at end) ----
        if (!have || nI != I) {
            #pragma unroll
            for (int d = 0; d < 8; d++) {
                denom[d] += __shfl_xor_sync(0xffffffffu, denom[d], 1);
                denom[d] += __shfl_xor_sync(0xffffffffu, denom[d], 2);
            }
            if ((lane & 3) == 0) {
                #pragma unroll
                for (int d = 0; d < 8; d++)
                    atomicAdd(&g_denom[row0 + (d >> 1) * 16 + (d & 1) * 8 + (lane >> 2)],
                              denom[d]);
            }
            #pragma unroll
            for (int d = 0; d < 8; d++) denom[d] = 0.0f;
        }

        __syncthreads();   // all warps done with A / Bbuf[cur] before refill

        if (have) {
            if (nI != I) {
                load_tile(A_base, nI * BM, tid);
                load_tile(Bbuf[cur ^ 1], nJ * BN, tid);
                CP_COMMIT();
            }
            cur ^= 1;
            I = nI; J = nJ;
        }
    }

    // ---- last CTA: final log/mean reduction ----
    __threadfence();
    __shared__ unsigned s_tick;
    if (tid == 0) s_tick = atomicAdd(&g_done, 1u);
    __syncthreads();
    if (s_tick == NUM_CTAS - 1) {
        float s = 0.0f;
        for (int r = tid; r < TWO_N; r += 256)
            s += logf(g_denom[r]) - g_pos[r & (NROWS - 1)] * TAU_INV;
        #pragma unroll
        for (int o = 16; o; o >>= 1) s += __shfl_xor_sync(0xffffffffu, s, o);
        __shared__ float red[8];
        if (lane == 0) red[warp] = s;
        __syncthreads();
        if (tid == 0) {
            float v = 0.0f;
            #pragma unroll
            for (int w = 0; w < 8; w++) v += red[w];
            out[0] = v * (1.0f / (float)TWO_N);
        }
    }
}

// ---------------- launch ----------------------------------------------------
extern "C" void kernel_launch(void* const* d_in, const int* in_sizes, int n_in,
                              void* d_out, int out_size) {
    (void)in_sizes; (void)n_in; (void)out_size;
    const float* x1 = (const float*)d_in[0];
    const float* x2 = (const float*)d_in[1];
    float* out = (float*)d_out;

    cudaFuncSetAttribute(gemm_kernel,
                         cudaFuncAttributeMaxDynamicSharedMemorySize, SMEM_TOTAL);

    dim3 wb(32, 8);
    norm_kernel<<<TWO_N / 8, wb>>>(x1, x2);
    pos_kernel<<<NROWS / 8, wb>>>(x1, x2);
    gemm_kernel<<<NUM_CTAS, 256, SMEM_TOTAL>>>(out);
}